// round 1
// baseline (speedup 1.0000x reference)
#include <cuda_runtime.h>

#define Hh 51
#define G4 204          // 4*H
#define NBATCH 4
#define NTH 224
#define BTOT 512

__device__ __forceinline__ unsigned long long pack2(float lo, float hi) {
    unsigned long long r;
    asm("mov.b64 %0, {%1,%2};" : "=l"(r) : "f"(lo), "f"(hi));
    return r;
}
__device__ __forceinline__ void ffma2(unsigned long long &acc, unsigned long long a, unsigned long long b) {
    asm("fma.rn.f32x2 %0, %1, %2, %0;" : "+l"(acc) : "l"(a), "l"(b));
}
__device__ __forceinline__ float sum2(unsigned long long a) {
    float lo, hi;
    asm("mov.b64 {%0,%1}, %2;" : "=f"(lo), "=f"(hi) : "l"(a));
    return lo + hi;
}
__device__ __forceinline__ void lds128(unsigned long long &p0, unsigned long long &p1, unsigned addr) {
    asm volatile("ld.shared.v2.b64 {%0,%1}, [%2];" : "=l"(p0), "=l"(p1) : "r"(addr));
}
__device__ __forceinline__ float fsig(float x) {
    return __fdividef(1.f, 1.f + __expf(-x));
}
__device__ __forceinline__ float ftanh_(float x) {
    float ax = fabsf(x);
    float e  = __expf(2.f * ax);                 // inf-safe: 2/(inf+1) -> 0
    float r  = 1.f - __fdividef(2.f, e + 1.f);   // tanh(|x|)
    return (x < 0.f) ? -r : r;
}

__global__ void __launch_bounds__(NTH, 1)
lstm2_kernel(const float* __restrict__ input,
             const float* __restrict__ W_ih1, const float* __restrict__ W_hh1,
             const float* __restrict__ b_ih1, const float* __restrict__ b_hh1,
             const float* __restrict__ W_ih2, const float* __restrict__ W_hh2,
             const float* __restrict__ b_ih2, const float* __restrict__ b_hh2,
             const float* __restrict__ W_lin, const float* __restrict__ b_lin,
             float* __restrict__ out, int T, int Ttot)
{
    // hcat[b][0..50] = h1, [51..101] = h2, [102..103] = 0 padding (x 0-weight)
    __shared__ __align__(16) float hcat[NBATCH][104];
    __shared__ float gbuf[NBATCH][G4];
    __shared__ float pbuf[NBATCH][68];   // stride 68: conflict-free for 4-lane column reads
    __shared__ float xnext[NBATCH];

    const int  tid     = threadIdx.x;
    const int  b0      = blockIdx.x * NBATCH;
    const int  g       = tid;
    const bool is_gate = (tid < G4);
    const int  b_u     = tid / Hh;          // update mapping (valid when tid<204)
    const int  j_u     = tid - b_u * Hh;

    // zero hcat (incl. padding)
    for (int i = tid; i < NBATCH * 104; i += NTH) (&hcat[0][0])[i] = 0.f;

    // ---- load weights into registers (packed along K) ----
    float wi1 = 0.f, bs1 = 0.f, bs2 = 0.f, wl = 0.f;
    unsigned long long w1p[26], w2p[52];
    if (is_gate) {
        wi1 = W_ih1[g];
        bs1 = b_ih1[g] + b_hh1[g];
        bs2 = b_ih2[g] + b_hh2[g];
        const float* r1 = W_hh1 + g * Hh;
        #pragma unroll
        for (int j = 0; j < 25; ++j) w1p[j] = pack2(r1[2*j], r1[2*j + 1]);
        w1p[25] = pack2(r1[50], 0.f);
        const float* ri = W_ih2 + g * Hh;   // multiplies h1
        const float* rh = W_hh2 + g * Hh;   // multiplies h2
        #pragma unroll
        for (int j = 0; j < 51; ++j) {
            const int k0 = 2*j, k1 = 2*j + 1;
            float a = (k0 < Hh) ? ri[k0] : rh[k0 - Hh];
            float c = (k1 < Hh) ? ri[k1] : rh[k1 - Hh];
            w2p[j] = pack2(a, c);
        }
        w2p[51] = pack2(0.f, 0.f);
        wl = W_lin[j_u];
    }
    const float blin = b_lin[0];
    float c1 = 0.f, c2 = 0.f;

    unsigned hbase[NBATCH];
    #pragma unroll
    for (int b = 0; b < NBATCH; ++b)
        hbase[b] = (unsigned)__cvta_generic_to_shared(&hcat[b][0]);

    __syncthreads();

    for (int t = 0; t < Ttot; ++t) {
        // feedback region: out(t-1) -> x(t), need xnext visible
        if (t >= T) __syncthreads();

        // ---- phase 1: layer-1 gates (K = 51 over h1) ----
        if (is_gate) {
            unsigned long long acc[NBATCH];
            #pragma unroll
            for (int b = 0; b < NBATCH; ++b) {
                float x = (t < T) ? input[(b0 + b) * T + t] : xnext[b];
                acc[b] = pack2(fmaf(x, wi1, bs1), 0.f);
            }
            #pragma unroll
            for (int kk = 0; kk < 13; ++kk) {
                #pragma unroll
                for (int b = 0; b < NBATCH; ++b) {
                    unsigned long long p0, p1;
                    lds128(p0, p1, hbase[b] + kk * 16);
                    ffma2(acc[b], w1p[2*kk],     p0);
                    ffma2(acc[b], w1p[2*kk + 1], p1);
                }
            }
            #pragma unroll
            for (int b = 0; b < NBATCH; ++b) gbuf[b][g] = sum2(acc[b]);
        }
        __syncthreads();

        // ---- phase 2: layer-1 cell update ----
        if (is_gate) {
            float gi = gbuf[b_u][j_u];
            float gf = gbuf[b_u][Hh   + j_u];
            float gg = gbuf[b_u][2*Hh + j_u];
            float go = gbuf[b_u][3*Hh + j_u];
            c1 = fsig(gf) * c1 + fsig(gi) * ftanh_(gg);
            hcat[b_u][j_u] = fsig(go) * ftanh_(c1);
        }
        __syncthreads();

        // ---- phase 3: layer-2 gates (K = 102 over [h1;h2]) ----
        if (is_gate) {
            unsigned long long acc[NBATCH];
            #pragma unroll
            for (int b = 0; b < NBATCH; ++b) acc[b] = pack2(bs2, 0.f);
            #pragma unroll
            for (int kk = 0; kk < 26; ++kk) {
                #pragma unroll
                for (int b = 0; b < NBATCH; ++b) {
                    unsigned long long p0, p1;
                    lds128(p0, p1, hbase[b] + kk * 16);
                    ffma2(acc[b], w2p[2*kk],     p0);
                    ffma2(acc[b], w2p[2*kk + 1], p1);
                }
            }
            #pragma unroll
            for (int b = 0; b < NBATCH; ++b) gbuf[b][g] = sum2(acc[b]);
        }
        __syncthreads();

        // ---- phase 4: layer-2 cell update + linear products ----
        if (is_gate) {
            float gi = gbuf[b_u][j_u];
            float gf = gbuf[b_u][Hh   + j_u];
            float gg = gbuf[b_u][2*Hh + j_u];
            float go = gbuf[b_u][3*Hh + j_u];
            c2 = fsig(gf) * c2 + fsig(gi) * ftanh_(gg);
            float h2 = fsig(go) * ftanh_(c2);
            hcat[b_u][Hh + j_u] = h2;
            pbuf[b_u][j_u] = wl * h2;
        }
        __syncthreads();

        // ---- phase 5: output dot on spare threads (overlaps next phase 1) ----
        if (tid >= G4 && tid < G4 + NBATCH) {
            int b = tid - G4;
            float s0 = 0.f, s1 = 0.f, s2 = 0.f, s3 = 0.f;
            #pragma unroll
            for (int j = 0; j < 48; j += 4) {
                s0 += pbuf[b][j];     s1 += pbuf[b][j + 1];
                s2 += pbuf[b][j + 2]; s3 += pbuf[b][j + 3];
            }
            float s = (s0 + s1) + (s2 + s3)
                    + pbuf[b][48] + pbuf[b][49] + pbuf[b][50] + blin;
            out[(b0 + b) * Ttot + t] = s;
            xnext[b] = s;
        }
    }
}

extern "C" void kernel_launch(void* const* d_in, const int* in_sizes, int n_in,
                              void* d_out, int out_size) {
    const float* input = (const float*)d_in[0];
    const float* W_ih1 = (const float*)d_in[1];
    const float* W_hh1 = (const float*)d_in[2];
    const float* b_ih1 = (const float*)d_in[3];
    const float* b_hh1 = (const float*)d_in[4];
    const float* W_ih2 = (const float*)d_in[5];
    const float* W_hh2 = (const float*)d_in[6];
    const float* b_ih2 = (const float*)d_in[7];
    const float* b_hh2 = (const float*)d_in[8];
    const float* W_lin = (const float*)d_in[9];
    const float* b_lin = (const float*)d_in[10];

    const int T    = in_sizes[0] / BTOT;   // 1024
    const int Ttot = out_size    / BTOT;   // 1088 = T + future

    lstm2_kernel<<<BTOT / NBATCH, NTH>>>(input, W_ih1, W_hh1, b_ih1, b_hh1,
                                         W_ih2, W_hh2, b_ih2, b_hh2,
                                         W_lin, b_lin,
                                         (float*)d_out, T, Ttot);
}

// round 2
// speedup vs baseline: 1.1222x; 1.1222x over previous
#include <cuda_runtime.h>

#define Hh 51
#define NB 4
#define NTH 224
#define BTOT 512
#define ROWF 104                        // floats per hcat row: [0..50]=h1, [51]=x, [52..102]=h2, [103]=0
#define BUF_BYTES (NB * ROWF * 4)       // bytes per double-buffer half

__device__ __forceinline__ unsigned long long pack2(float lo, float hi) {
    unsigned long long r;
    asm("mov.b64 %0, {%1,%2};" : "=l"(r) : "f"(lo), "f"(hi));
    return r;
}
__device__ __forceinline__ void ffma2(unsigned long long &acc, unsigned long long a, unsigned long long b) {
    asm("fma.rn.f32x2 %0, %1, %2, %0;" : "+l"(acc) : "l"(a), "l"(b));
}
__device__ __forceinline__ float sum2(unsigned long long a) {
    float lo, hi;
    asm("mov.b64 {%0,%1}, %2;" : "=f"(lo), "=f"(hi) : "l"(a));
    return lo + hi;
}
__device__ __forceinline__ void lds128(unsigned long long &p0, unsigned long long &p1, unsigned addr) {
    asm volatile("ld.shared.v2.b64 {%0,%1}, [%2];" : "=l"(p0), "=l"(p1) : "r"(addr));
}
__device__ __forceinline__ float fsig(float x) {
    return __fdividef(1.f, 1.f + __expf(-x));
}
__device__ __forceinline__ float ftanh_(float x) {
    float ax = fabsf(x);
    float e  = __expf(2.f * ax);
    float r  = 1.f - __fdividef(2.f, e + 1.f);
    return (x < 0.f) ? -r : r;
}

// 4x4 transpose across lane groups differing in bits 3..4.
// In: v[b] = my gate-row's dot for batch b. Out: v[g] = gate g's dot for batch q=(lane>>3)&3.
__device__ __forceinline__ void transp4(float v[4], int lane) {
    {
        bool lo = lane & 8;
        float tA = lo ? v[0] : v[1];
        float tB = lo ? v[2] : v[3];
        tA = __shfl_xor_sync(0xffffffffu, tA, 8);
        tB = __shfl_xor_sync(0xffffffffu, tB, 8);
        if (lo) { v[0] = tA; v[2] = tB; } else { v[1] = tA; v[3] = tB; }
    }
    {
        bool hi = lane & 16;
        float uA = hi ? v[0] : v[2];
        float uB = hi ? v[1] : v[3];
        uA = __shfl_xor_sync(0xffffffffu, uA, 16);
        uB = __shfl_xor_sync(0xffffffffu, uB, 16);
        if (hi) { v[0] = uA; v[1] = uB; } else { v[2] = uA; v[3] = uB; }
    }
}

__global__ void __launch_bounds__(NTH, 1)
lstm2_kernel(const float* __restrict__ input,
             const float* __restrict__ W_ih1, const float* __restrict__ W_hh1,
             const float* __restrict__ b_ih1, const float* __restrict__ b_hh1,
             const float* __restrict__ W_ih2, const float* __restrict__ W_hh2,
             const float* __restrict__ b_ih2, const float* __restrict__ b_hh2,
             const float* __restrict__ W_lin, const float* __restrict__ b_lin,
             float* __restrict__ out, int T, int Ttot)
{
    __shared__ __align__(16) float hcat[2][NB][ROWF];   // double-buffered
    __shared__ __align__(16) float pbuf[NB][68];        // W_lin-weighted h2 products

    const int  tid  = threadIdx.x;
    const int  lane = tid & 31;
    const int  wid  = tid >> 5;
    const int  jloc = lane & 7;
    const int  q    = (lane >> 3) & 3;          // gate index for dots; batch index for update
    const int  j    = wid * 8 + jloc;
    const bool act  = (j < Hh);
    const int  b0   = blockIdx.x * NB;
    const int  row  = q * Hh + (act ? j : 0);   // this lane's gate row

    const bool pre_lane = (wid == 6) && (jloc == 3);    // x(t+1) prefetch, batch q
    const bool red_lane = (wid == 6) && (jloc == 4);    // output reduction, batch q

    for (int i = tid; i < 2 * NB * ROWF; i += NTH) (&hcat[0][0][0])[i] = 0.f;
    if (tid < NB) hcat[1][tid][51] = input[(b0 + tid) * T];   // x(0) into prev-buffer of t=0

    // ---- weights, packed along K into 64-bit pairs (registers) ----
    unsigned long long w1p[26], w2p[52];
    {
        const float* r1 = W_hh1 + row * Hh;
        #pragma unroll
        for (int k = 0; k < 25; ++k)
            w1p[k] = pack2(act ? r1[2*k] : 0.f, act ? r1[2*k + 1] : 0.f);
        w1p[25] = pack2(act ? r1[50] : 0.f, act ? W_ih1[row] : 0.f);   // x folded in
        const float* ri = W_ih2 + row * Hh;   // multiplies h1
        const float* rh = W_hh2 + row * Hh;   // multiplies h2
        #pragma unroll
        for (int k = 0; k < 52; ++k) {
            int k0 = 2*k, k1 = 2*k + 1;
            float a = 0.f, b = 0.f;
            if (act) {
                a = (k0 < 51) ? ri[k0] : ((k0 >= 52 && k0 <= 102) ? rh[k0 - 52] : 0.f);
                b = (k1 < 51) ? ri[k1] : ((k1 >= 52 && k1 <= 102) ? rh[k1 - 52] : 0.f);
            }
            w2p[k] = pack2(a, b);
        }
    }
    const float bs1  = act ? (b_ih1[row] + b_hh1[row]) : 0.f;
    const float bs2  = act ? (b_ih2[row] + b_hh2[row]) : 0.f;
    const float wl   = act ? W_lin[j] : 0.f;
    const float blin = b_lin[0];

    unsigned hb[NB];
    #pragma unroll
    for (int b = 0; b < NB; ++b)
        hb[b] = (unsigned)__cvta_generic_to_shared(&hcat[0][b][0]);

    float c1 = 0.f, c2 = 0.f, xpre = 0.f;
    __syncthreads();

    for (int t = 0; t < Ttot; ++t) {
        const unsigned co = (t & 1) ? (unsigned)BUF_BYTES : 0u;   // cur buffer
        const unsigned po = co ^ (unsigned)BUF_BYTES;             // prev buffer

        // ---- spare duties (warp 6), overlapped with phase A ----
        if (pre_lane && (t + 1 < T))
            xpre = input[(b0 + q) * T + (t + 1)];
        if (red_lane && t >= 1 && t < T) {       // deferred output for step t-1
            float4 s4 = make_float4(0.f, 0.f, 0.f, 0.f);
            const float4* p4 = (const float4*)&pbuf[q][0];
            #pragma unroll
            for (int k = 0; k < 12; ++k) {
                float4 v4 = p4[k];
                s4.x += v4.x; s4.y += v4.y; s4.z += v4.z; s4.w += v4.w;
            }
            float s = (s4.x + s4.y) + (s4.z + s4.w)
                    + pbuf[q][48] + pbuf[q][49] + pbuf[q][50] + blin;
            out[(b0 + q) * Ttot + (t - 1)] = s;
        }

        // ---- phase A: layer-1 full dot (prev floats 0..51, x included)
        //               + layer-2 h2-half dot (prev floats 52..103) ----
        unsigned long long a1[NB], a2[NB];
        #pragma unroll
        for (int b = 0; b < NB; ++b) { a1[b] = pack2(bs1, 0.f); a2[b] = pack2(bs2, 0.f); }
        #pragma unroll
        for (int kk = 0; kk < 13; ++kk) {
            #pragma unroll
            for (int b = 0; b < NB; ++b) {
                unsigned long long p0, p1, q0, q1;
                lds128(p0, p1, hb[b] + po + kk * 16);
                lds128(q0, q1, hb[b] + po + 208 + kk * 16);
                ffma2(a1[b], w1p[2*kk],      p0);
                ffma2(a1[b], w1p[2*kk + 1],  p1);
                ffma2(a2[b], w2p[26 + 2*kk], q0);
                ffma2(a2[b], w2p[27 + 2*kk], q1);
            }
        }
        float v[4];
        #pragma unroll
        for (int b = 0; b < NB; ++b) v[b] = sum2(a1[b]);
        transp4(v, lane);                         // v = [i,f,g,o] for (batch q, row j)
        {
            float cg = fsig(v[1]) * c1 + fsig(v[0]) * ftanh_(v[2]);
            c1 = cg;
            float h1 = fsig(v[3]) * ftanh_(cg);
            if (act) hcat[t & 1][q][j] = h1;      // new h1 -> cur buffer
        }
        __syncthreads();                          // B_A

        // ---- phase B: layer-2 h1-half dot (cur floats 0..51; x slot has weight 0) ----
        if (pre_lane && (t + 1 < T)) hcat[t & 1][q][51] = xpre;   // x(t+1) -> cur buffer
        #pragma unroll
        for (int kk = 0; kk < 13; ++kk) {
            #pragma unroll
            for (int b = 0; b < NB; ++b) {
                unsigned long long p0, p1;
                lds128(p0, p1, hb[b] + co + kk * 16);
                ffma2(a2[b], w2p[2*kk],     p0);
                ffma2(a2[b], w2p[2*kk + 1], p1);
            }
        }
        #pragma unroll
        for (int b = 0; b < NB; ++b) v[b] = sum2(a2[b]);
        transp4(v, lane);
        {
            float cg = fsig(v[1]) * c2 + fsig(v[0]) * ftanh_(v[2]);
            c2 = cg;
            float h2v = fsig(v[3]) * ftanh_(cg);
            if (act) {
                hcat[t & 1][q][52 + j] = h2v;     // new h2 -> cur buffer
                pbuf[q][j] = wl * h2v;
            }
        }
        __syncthreads();                          // B_B

        // ---- autoregressive tail: out(t) feeds x(t+1) ----
        if (t >= T - 1) {
            if (red_lane) {
                float4 s4 = make_float4(0.f, 0.f, 0.f, 0.f);
                const float4* p4 = (const float4*)&pbuf[q][0];
                #pragma unroll
                for (int k = 0; k < 12; ++k) {
                    float4 v4 = p4[k];
                    s4.x += v4.x; s4.y += v4.y; s4.z += v4.z; s4.w += v4.w;
                }
                float s = (s4.x + s4.y) + (s4.z + s4.w)
                        + pbuf[q][48] + pbuf[q][49] + pbuf[q][50] + blin;
                out[(b0 + q) * Ttot + t] = s;
                hcat[t & 1][q][51] = s;           // x(t+1)
            }
            __syncthreads();                      // B_C (AR region only)
        }
    }
}

extern "C" void kernel_launch(void* const* d_in, const int* in_sizes, int n_in,
                              void* d_out, int out_size) {
    const float* input = (const float*)d_in[0];
    const float* W_ih1 = (const float*)d_in[1];
    const float* W_hh1 = (const float*)d_in[2];
    const float* b_ih1 = (const float*)d_in[3];
    const float* b_hh1 = (const float*)d_in[4];
    const float* W_ih2 = (const float*)d_in[5];
    const float* W_hh2 = (const float*)d_in[6];
    const float* b_ih2 = (const float*)d_in[7];
    const float* b_hh2 = (const float*)d_in[8];
    const float* W_lin = (const float*)d_in[9];
    const float* b_lin = (const float*)d_in[10];

    const int T    = in_sizes[0] / BTOT;   // 1024
    const int Ttot = out_size    / BTOT;   // 1088

    lstm2_kernel<<<BTOT / NB, NTH>>>(input, W_ih1, W_hh1, b_ih1, b_hh1,
                                     W_ih2, W_hh2, b_ih2, b_hh2,
                                     W_lin, b_lin,
                                     (float*)d_out, T, Ttot);
}